// round 16
// baseline (speedup 1.0000x reference)
#include <cuda_runtime.h>
#include <cuda_fp16.h>
#include <cstdio>
#include <cstdlib>
#include <cstdint>
#include <cmath>

#define Nn   100000
#define Ee   1600000
#define Hd   64
#define Ll   8
#define OUTD 40

// ---------------- scratch (static device globals; no allocation) ----------------
__device__ int   g_deg[Nn];
__device__ float g_dis[Nn];
__device__ int   g_rowptr[Nn + 1];
__device__ int   g_cursor[Nn];
__device__ __align__(16) int2   g_ew[Ee];                    // {src, float_bits(norm)}
__device__ int   g_bsum[128];
__device__ __align__(16) __half g_w16[57344];                // W0|Ws|lin_w in fp16
__device__ __align__(16) __half g_tmp[(size_t)Nn * Hd];      // h @ W (gather payload)
__device__ __align__(16) __half g_tmp2[(size_t)Nn * Hd];     // double buffer
__device__ __align__(16) __half g_hall[(size_t)Ll * Nn * Hd];// per-layer h (JK)
__device__ int   g_is64;

#define SW(o) ((o) ^ (((o) >> 3) & 0x70))

// ---------------- mma/ldmatrix helpers ----------------
__device__ __forceinline__ uint32_t s2u(const void* p) {
    uint32_t a;
    asm("{ .reg .u64 t; cvta.to.shared.u64 t, %1; cvt.u32.u64 %0, t; }" : "=r"(a) : "l"(p));
    return a;
}
__device__ __forceinline__ void ldsm_x4(uint32_t& a0, uint32_t& a1, uint32_t& a2,
                                        uint32_t& a3, uint32_t addr) {
    asm volatile("ldmatrix.sync.aligned.m8n8.x4.shared.b16 {%0,%1,%2,%3},[%4];"
                 : "=r"(a0), "=r"(a1), "=r"(a2), "=r"(a3) : "r"(addr));
}
__device__ __forceinline__ void ldsm_x2t(uint32_t& b0, uint32_t& b1, uint32_t addr) {
    asm volatile("ldmatrix.sync.aligned.m8n8.x2.trans.shared.b16 {%0,%1},[%2];"
                 : "=r"(b0), "=r"(b1) : "r"(addr));
}
__device__ __forceinline__ void mma16816(float* d, uint32_t a0, uint32_t a1, uint32_t a2,
                                         uint32_t a3, uint32_t b0, uint32_t b1) {
    asm volatile(
        "mma.sync.aligned.m16n8k16.row.col.f32.f16.f16.f32 "
        "{%0,%1,%2,%3},{%4,%5,%6,%7},{%8,%9},{%0,%1,%2,%3};"
        : "+f"(d[0]), "+f"(d[1]), "+f"(d[2]), "+f"(d[3])
        : "r"(a0), "r"(a1), "r"(a2), "r"(a3), "r"(b0), "r"(b1));
}

// ---------------- dtype probe ----------------
__global__ void k_detect(const unsigned int* __restrict__ p) {
    __shared__ unsigned int s;
    if (threadIdx.x == 0) s = 0u;
    __syncthreads();
    unsigned int v = 0u;
    for (int e = threadIdx.x; e < 2048; e += 256) v |= p[2 * e + 1];
    atomicOr(&s, v);
    __syncthreads();
    if (threadIdx.x == 0) g_is64 = (s == 0u) ? 1 : 0;
}
__device__ __forceinline__ int ld_src(const int* p, int e) {
    return g_is64 ? p[2 * e] : p[e];
}
__device__ __forceinline__ int ld_dst(const int* p, int e) {
    return g_is64 ? p[2 * Ee + 2 * e] : p[Ee + e];
}

// ---------------- weight convert (fp32 -> fp16) ----------------
__global__ void k_cvt_w(const float* __restrict__ W0, const float* __restrict__ Ws,
                        const float* __restrict__ lw) {
    int i = blockIdx.x * 256 + threadIdx.x;
    if (i >= 57344) return;
    float v;
    if (i < 8192) v = W0[i];
    else if (i < 36864) v = Ws[i - 8192];
    else v = lw[i - 36864];
    g_w16[i] = __float2half(v);
}

// ---------------- degree / CSR ----------------
__global__ void k_count(const int* __restrict__ ei) {
    int e = blockIdx.x * 256 + threadIdx.x;
    if (e < Ee) atomicAdd(&g_deg[ld_dst(ei, e)], 1);
}
__global__ void k_scan_block() {
    __shared__ int s[1024];
    int i = blockIdx.x * 1024 + threadIdx.x;
    int v = (i < Nn) ? g_deg[i] : 0;
    if (i < Nn) g_dis[i] = rsqrtf((float)(v + 1));
    s[threadIdx.x] = v;
    __syncthreads();
    for (int off = 1; off < 1024; off <<= 1) {
        int t = (threadIdx.x >= off) ? s[threadIdx.x - off] : 0;
        __syncthreads();
        s[threadIdx.x] += t;
        __syncthreads();
    }
    if (i < Nn) g_rowptr[i] = s[threadIdx.x] - v;
    if (threadIdx.x == 1023) g_bsum[blockIdx.x] = s[1023];
}
__global__ void k_add_off() {
    __shared__ int sb[128];
    int t = threadIdx.x;
    if (t < 128) sb[t] = (t < (int)blockIdx.x) ? g_bsum[t] : 0;
    __syncthreads();
    for (int off = 64; off > 0; off >>= 1) {
        if (t < off) sb[t] += sb[t + off];
        __syncthreads();
    }
    int base = sb[0];
    int i = blockIdx.x * 1024 + t;
    if (i < Nn) {
        int r = g_rowptr[i] + base;
        g_rowptr[i] = r;
        g_cursor[i] = r;
    }
    if (i == 0) g_rowptr[Nn] = Ee;
}
__global__ void k_fill(const int* __restrict__ ei) {
    int e = blockIdx.x * 256 + threadIdx.x;
    if (e >= Ee) return;
    int s = ld_src(ei, e);
    int d = ld_dst(ei, e);
    int p = atomicAdd(&g_cursor[d], 1);
    g_ew[p] = make_int2(s, __float_as_int(g_dis[s] * g_dis[d]));
}

// ------- GEMM0 (fused cvt): tmp[fp16] = fp16(x[N,128]) @ W0_16[128,64] -------
__global__ void k_gemm0_tc(const float* __restrict__ A, const __half* __restrict__ B,
                           __half2* __restrict__ C) {
    __shared__ __align__(16) uint8_t sA[2 * 16384];  // 2 panels: 128 rows x 128B
    __shared__ __align__(16) uint8_t sB[128 * 128];
    const int row0 = blockIdx.x * 128;
    const int tid = threadIdx.x;
    for (int ci = tid; ci < 128 * 32; ci += 256) {
        int r = ci >> 5, c4 = ci & 31;
        float4 v = make_float4(0.f, 0.f, 0.f, 0.f);
        if (row0 + r < Nn) v = ((const float4*)(A + (size_t)(row0 + r) * 128))[c4];
        __half2 h0 = __floats2half2_rn(v.x, v.y);
        __half2 h1 = __floats2half2_rn(v.z, v.w);
        uint2 u = make_uint2(*(uint32_t*)&h0, *(uint32_t*)&h1);
        *(uint2*)(sA + (c4 >> 4) * 16384 + SW(r * 128 + (c4 & 15) * 8)) = u;
    }
    for (int ci = tid; ci < 128 * 8; ci += 256) {
        int r = ci >> 3, c = ci & 7;
        uint4 v = ((const uint4*)(B + r * 64))[c];
        *(uint4*)(sB + SW(r * 128 + c * 16)) = v;
    }
    __syncthreads();

    const int warp = tid >> 5, lane = tid & 31;
    const int m_local = warp * 16;
    const uint32_t sAu = s2u(sA), sBu = s2u(sB);
    const int arow = m_local + (lane & 15);
    const int acol16 = (lane >> 4) * 16;
    float acc[8][4];
#pragma unroll
    for (int i = 0; i < 8; i++)
#pragma unroll
        for (int j = 0; j < 4; j++) acc[i][j] = 0.f;

#pragma unroll
    for (int ks = 0; ks < 8; ks++) {
        int k0 = ks * 16;
        uint32_t a0, a1, a2, a3;
        ldsm_x4(a0, a1, a2, a3,
                sAu + (k0 >> 6) * 16384 + SW(arow * 128 + (k0 & 63) * 2 + acol16));
#pragma unroll
        for (int nt = 0; nt < 8; nt++) {
            uint32_t b0, b1;
            ldsm_x2t(b0, b1, sBu + SW((k0 + (lane & 15)) * 128 + nt * 16));
            mma16816(acc[nt], a0, a1, a2, a3, b0, b1);
        }
    }
    const int g = lane >> 2, t4 = lane & 3;
    int r0 = row0 + m_local + g, r1 = r0 + 8;
    if (r0 < Nn) {
#pragma unroll
        for (int nt = 0; nt < 8; nt++)
            C[(size_t)r0 * 32 + nt * 4 + t4] = __floats2half2_rn(acc[nt][0], acc[nt][1]);
    }
    if (r1 < Nn) {
#pragma unroll
        for (int nt = 0; nt < 8; nt++)
            C[(size_t)r1 * 32 + nt * 4 + t4] = __floats2half2_rn(acc[nt][2], acc[nt][3]);
    }
}

// ------- fused aggregate + layer GEMM -------
// Phase 1: h[row0..row0+128) = relu(A_hat * tmpin + bias); write to hall + smem (swizzled)
// Phase 2 (!LAST): tmpout = h @ Bw   (mma from smem)
template <bool LAST>
__global__ void k_agg_gemm(const float* __restrict__ bias, const __half* __restrict__ tmpin,
                           const __half* __restrict__ Bw, uint4* __restrict__ hall_slot,
                           __half2* __restrict__ tmpout) {
    __shared__ __align__(16) uint8_t sA[16384];  // 128 rows x 128B (h tile)
    __shared__ __align__(16) uint8_t sB[8192];   // 64 k-rows x 128B (W)
    const int row0 = blockIdx.x * 128;
    const int tid = threadIdx.x;
    const int warp = tid >> 5, lane = tid & 31;
    const int fl = lane & 7;
    const uint4* tp = (const uint4*)tmpin;

    if (!LAST) {
        for (int ci = tid; ci < 512; ci += 256) {
            int r = ci >> 3, c = ci & 7;
            uint4 v = ((const uint4*)(Bw + r * 64))[c];
            *(uint4*)(sB + SW(r * 128 + c * 16)) = v;
        }
    }

    const float4 bb0 = *(const float4*)&bias[fl * 8];
    const float4 bb1 = *(const float4*)&bias[fl * 8 + 4];

#pragma unroll
    for (int iter = 0; iter < 4; iter++) {
        int local = warp * 16 + iter * 4 + (lane >> 3);
        int node = row0 + local;
        uint4 res = make_uint4(0, 0, 0, 0);
        if (node < Nn) {
            float a0 = 0.f, a1 = 0.f, a2 = 0.f, a3 = 0.f, a4 = 0.f, a5 = 0.f, a6 = 0.f,
                  a7 = 0.f;
            int beg = g_rowptr[node], end = g_rowptr[node + 1];
            for (int j = beg; j < end; j++) {
                int2 e = __ldg(&g_ew[j]);
                float wt = __int_as_float(e.y);
                uint4 v = __ldg(&tp[(size_t)e.x * 8 + fl]);
                float2 p0 = __half22float2(*(__half2*)&v.x);
                float2 p1 = __half22float2(*(__half2*)&v.y);
                float2 p2 = __half22float2(*(__half2*)&v.z);
                float2 p3 = __half22float2(*(__half2*)&v.w);
                a0 += wt * p0.x; a1 += wt * p0.y;
                a2 += wt * p1.x; a3 += wt * p1.y;
                a4 += wt * p2.x; a5 += wt * p2.y;
                a6 += wt * p3.x; a7 += wt * p3.y;
            }
            float d = g_dis[node];
            float sw = d * d;  // self-loop norm
            {
                uint4 v = tp[(size_t)node * 8 + fl];
                float2 p0 = __half22float2(*(__half2*)&v.x);
                float2 p1 = __half22float2(*(__half2*)&v.y);
                float2 p2 = __half22float2(*(__half2*)&v.z);
                float2 p3 = __half22float2(*(__half2*)&v.w);
                a0 += sw * p0.x; a1 += sw * p0.y;
                a2 += sw * p1.x; a3 += sw * p1.y;
                a4 += sw * p2.x; a5 += sw * p2.y;
                a6 += sw * p3.x; a7 += sw * p3.y;
            }
            __half2 h0 = __floats2half2_rn(fmaxf(a0 + bb0.x, 0.f), fmaxf(a1 + bb0.y, 0.f));
            __half2 h1 = __floats2half2_rn(fmaxf(a2 + bb0.z, 0.f), fmaxf(a3 + bb0.w, 0.f));
            __half2 h2 = __floats2half2_rn(fmaxf(a4 + bb1.x, 0.f), fmaxf(a5 + bb1.y, 0.f));
            __half2 h3 = __floats2half2_rn(fmaxf(a6 + bb1.z, 0.f), fmaxf(a7 + bb1.w, 0.f));
            res = make_uint4(*(uint32_t*)&h0, *(uint32_t*)&h1, *(uint32_t*)&h2,
                             *(uint32_t*)&h3);
            hall_slot[(size_t)node * 8 + fl] = res;
        }
        *(uint4*)(sA + SW(local * 128 + fl * 16)) = res;
    }
    __syncthreads();
    if (LAST) return;

    const int m_local = warp * 16;
    const uint32_t sAu = s2u(sA), sBu = s2u(sB);
    const int arow = m_local + (lane & 15);
    const int acol16 = (lane >> 4) * 16;
    float acc[8][4];
#pragma unroll
    for (int i = 0; i < 8; i++)
#pragma unroll
        for (int j = 0; j < 4; j++) acc[i][j] = 0.f;

#pragma unroll
    for (int ks = 0; ks < 4; ks++) {
        int k0 = ks * 16;
        uint32_t a0, a1, a2, a3;
        ldsm_x4(a0, a1, a2, a3, sAu + SW(arow * 128 + k0 * 2 + acol16));
#pragma unroll
        for (int nt = 0; nt < 8; nt++) {
            uint32_t b0, b1;
            ldsm_x2t(b0, b1, sBu + SW((k0 + (lane & 15)) * 128 + nt * 16));
            mma16816(acc[nt], a0, a1, a2, a3, b0, b1);
        }
    }
    const int g = lane >> 2, t4 = lane & 3;
    int r0 = row0 + m_local + g, r1 = r0 + 8;
    if (r0 < Nn) {
#pragma unroll
        for (int nt = 0; nt < 8; nt++)
            tmpout[(size_t)r0 * 32 + nt * 4 + t4] =
                __floats2half2_rn(acc[nt][0], acc[nt][1]);
    }
    if (r1 < Nn) {
#pragma unroll
        for (int nt = 0; nt < 8; nt++)
            tmpout[(size_t)r1 * 32 + nt * 4 + t4] =
                __floats2half2_rn(acc[nt][2], acc[nt][3]);
    }
}

// ------- JK tensor-core GEMM: out[N,40] = concat_l(h_l)[N,512] @ lw[512,40] + lin_b -------
__global__ void k_jk_tc(const __half* __restrict__ hall, const __half* __restrict__ lw,
                        const float* __restrict__ lin_b, float* __restrict__ out) {
    __shared__ __align__(16) uint8_t sA[16384];
    __shared__ __align__(16) uint8_t sB[8192];
    const int row0 = blockIdx.x * 128;
    const int tid = threadIdx.x;
    const int warp = tid >> 5, lane = tid & 31;
    const int m_local = warp * 16;
    const uint32_t sAu = s2u(sA), sBu = s2u(sB);
    const int arow = m_local + (lane & 15);
    const int acol16 = (lane >> 4) * 16;
    float acc[5][4];
#pragma unroll
    for (int i = 0; i < 5; i++)
#pragma unroll
        for (int j = 0; j < 4; j++) acc[i][j] = 0.f;

    for (int slot = 0; slot < Ll; slot++) {
        for (int ci = tid; ci < 1024; ci += 256) {
            int r = ci >> 3, c = ci & 7;
            uint4 v = make_uint4(0, 0, 0, 0);
            if (row0 + r < Nn)
                v = ((const uint4*)(hall + ((size_t)slot * Nn + row0 + r) * 64))[c];
            *(uint4*)(sA + SW(r * 128 + c * 16)) = v;
        }
        for (int ci = tid; ci < 512; ci += 256) {
            int r = ci >> 3, c = ci & 7;
            uint4 v = make_uint4(0, 0, 0, 0);
            if (c < 5) v = ((const uint4*)(lw + (size_t)(slot * 64 + r) * OUTD))[c];
            *(uint4*)(sB + SW(r * 128 + c * 16)) = v;
        }
        __syncthreads();
#pragma unroll
        for (int ks = 0; ks < 4; ks++) {
            int k0 = ks * 16;
            uint32_t a0, a1, a2, a3;
            ldsm_x4(a0, a1, a2, a3, sAu + SW(arow * 128 + k0 * 2 + acol16));
#pragma unroll
            for (int nt = 0; nt < 5; nt++) {
                uint32_t b0, b1;
                ldsm_x2t(b0, b1, sBu + SW((k0 + (lane & 15)) * 128 + nt * 16));
                mma16816(acc[nt], a0, a1, a2, a3, b0, b1);
            }
        }
        __syncthreads();
    }
    const int g = lane >> 2, t4 = lane & 3;
    int r0 = row0 + m_local + g, r1 = r0 + 8;
#pragma unroll
    for (int nt = 0; nt < 5; nt++) {
        int c = nt * 8 + t4 * 2;
        float bl0 = lin_b[c], bl1 = lin_b[c + 1];
        if (r0 < Nn)
            *(float2*)&out[(size_t)r0 * OUTD + c] =
                make_float2(acc[nt][0] + bl0, acc[nt][1] + bl1);
        if (r1 < Nn)
            *(float2*)&out[(size_t)r1 * OUTD + c] =
                make_float2(acc[nt][2] + bl0, acc[nt][3] + bl1);
    }
}

extern "C" void kernel_launch(void* const* d_in, const int* in_sizes, int n_in,
                              void* d_out, int out_size) {
    const float* x = nullptr;
    const float* W0 = nullptr;
    const float* Ws = nullptr;
    const float* bs = nullptr;
    const float* lin_w = nullptr;
    const float* lin_b = nullptr;
    const int*   ei = nullptr;
    for (int i = 0; i < n_in; i++) {
        switch (in_sizes[i]) {
            case 12800000: x     = (const float*)d_in[i]; break;
            case 8192:     W0    = (const float*)d_in[i]; break;
            case 28672:    Ws    = (const float*)d_in[i]; break;
            case 512:      bs    = (const float*)d_in[i]; break;
            case 20480:    lin_w = (const float*)d_in[i]; break;
            case 40:       lin_b = (const float*)d_in[i]; break;
            case 3200000:
            case 6400000:  ei    = (const int*)d_in[i];   break;
            default: break;
        }
    }
    if (!(x && W0 && Ws && bs && lin_w && lin_b && ei)) {
        x     = (const float*)d_in[0];
        W0    = (const float*)d_in[1];
        Ws    = (const float*)d_in[2];
        bs    = (const float*)d_in[3];
        lin_w = (const float*)d_in[4];
        lin_b = (const float*)d_in[5];
        ei    = (const int*)d_in[6];
    }
    float* out = (float*)d_out;

    // device-symbol addresses for host-side kernel args (R7 root cause)
    __half *w16_d, *tmp_d, *tmp2_d, *hall_d;
    int* deg_d;
    cudaGetSymbolAddress((void**)&w16_d, g_w16);
    cudaGetSymbolAddress((void**)&tmp_d, g_tmp);
    cudaGetSymbolAddress((void**)&tmp2_d, g_tmp2);
    cudaGetSymbolAddress((void**)&hall_d, g_hall);
    cudaGetSymbolAddress((void**)&deg_d, g_deg);

    cudaStreamCaptureStatus cst = cudaStreamCaptureStatusNone;
    cudaError_t qe = cudaStreamIsCapturing((cudaStream_t)0, &cst);
    bool capturing = (qe != cudaSuccess) || (cst != cudaStreamCaptureStatusNone);
    if (qe != cudaSuccess) (void)cudaGetLastError();

    const int NB = (Nn + 1023) / 1024;       // 98
    const int GEMM_GRID = (Nn + 127) / 128;  // 782

    k_detect<<<1, 256>>>((const unsigned int*)ei);                   // 1
    cudaMemsetAsync(deg_d, 0, Nn * sizeof(int), 0);                  // 2
    k_cvt_w<<<224, 256>>>(W0, Ws, lin_w);                            // 3
    k_count<<<(Ee + 255) / 256, 256>>>(ei);                          // 4
    k_gemm0_tc<<<GEMM_GRID, 256>>>(x, w16_d, (__half2*)tmp_d);       // 5 <- profiled
    k_scan_block<<<NB, 1024>>>();                                    // 6
    k_add_off<<<NB, 1024>>>();                                       // 7
    k_fill<<<(Ee + 255) / 256, 256>>>(ei);                           // 8

    // ping-pong tmp buffers across layers
    __half* tin = tmp_d;
    __half* tout = tmp2_d;
    for (int l = 0; l < Ll; l++) {
        uint4* slot = (uint4*)(hall_d + (size_t)l * Nn * Hd);
        if (l < Ll - 1) {
            k_agg_gemm<false><<<GEMM_GRID, 256>>>(bs + l * Hd, tin,
                                                  w16_d + 8192 + (size_t)l * 4096, slot,
                                                  (__half2*)tout);
            __half* t = tin; tin = tout; tout = t;
        } else {
            k_agg_gemm<true><<<GEMM_GRID, 256>>>(bs + l * Hd, tin, nullptr, slot, nullptr);
        }
    }
    k_jk_tc<<<GEMM_GRID, 256>>>(hall_d, w16_d + 36864, lin_b, out);

    // -------- zero-output tripwire (correctness call only; never during capture) --------
    if (!capturing) {
        static float ho[8];
        cudaMemcpyAsync(ho, out, 8 * sizeof(float), cudaMemcpyDeviceToHost, 0);
        cudaError_t qs = cudaErrorNotReady;
        for (long it = 0; it < 4000000000L; it++) {
            qs = cudaStreamQuery((cudaStream_t)0);
            if (qs != cudaErrorNotReady) break;
        }
        float mx = 0.f;
        for (int i = 0; i < 8; i++) mx = fmaxf(mx, fabsf(ho[i]));
        if (qs != cudaSuccess || mx < 1e-6f) {
            fprintf(stderr, "[diag] TRIPWIRE mx=%g q=%s out=%g %g %g %g\n", mx,
                    cudaGetErrorName(qs), ho[0], ho[1], ho[2], ho[3]);
            fflush(stderr);
            abort();
        }
    }
}

// round 17
// speedup vs baseline: 1.3066x; 1.3066x over previous
#include <cuda_runtime.h>
#include <cuda_fp16.h>
#include <cstdio>
#include <cstdlib>
#include <cstdint>
#include <cmath>

#define Nn   100000
#define Ee   1600000
#define Hd   64
#define Ll   8
#define OUTD 40

// ---------------- scratch (static device globals; no allocation) ----------------
__device__ int   g_deg[Nn];
__device__ float g_dis[Nn];
__device__ int   g_rowptr[Nn + 1];
__device__ int   g_cursor[Nn];
__device__ __align__(16) int2   g_ew[Ee];                    // {src, float_bits(norm)}
__device__ int   g_bsum[128];
__device__ __align__(16) __half g_w16[57344];                // W0|Ws|lin_w in fp16
__device__ __align__(16) __half g_tmp[(size_t)Nn * Hd];      // h @ W (gather payload)
__device__ __align__(16) __half g_hall[(size_t)Ll * Nn * Hd];// per-layer h (JK)
__device__ int   g_is64;

#define SW(o) ((o) ^ (((o) >> 3) & 0x70))

// ---------------- mma/ldmatrix helpers ----------------
__device__ __forceinline__ uint32_t s2u(const void* p) {
    uint32_t a;
    asm("{ .reg .u64 t; cvta.to.shared.u64 t, %1; cvt.u32.u64 %0, t; }" : "=r"(a) : "l"(p));
    return a;
}
__device__ __forceinline__ void ldsm_x4(uint32_t& a0, uint32_t& a1, uint32_t& a2,
                                        uint32_t& a3, uint32_t addr) {
    asm volatile("ldmatrix.sync.aligned.m8n8.x4.shared.b16 {%0,%1,%2,%3},[%4];"
                 : "=r"(a0), "=r"(a1), "=r"(a2), "=r"(a3) : "r"(addr));
}
__device__ __forceinline__ void ldsm_x2t(uint32_t& b0, uint32_t& b1, uint32_t addr) {
    asm volatile("ldmatrix.sync.aligned.m8n8.x2.trans.shared.b16 {%0,%1},[%2];"
                 : "=r"(b0), "=r"(b1) : "r"(addr));
}
__device__ __forceinline__ void mma16816(float* d, uint32_t a0, uint32_t a1, uint32_t a2,
                                         uint32_t a3, uint32_t b0, uint32_t b1) {
    asm volatile(
        "mma.sync.aligned.m16n8k16.row.col.f32.f16.f16.f32 "
        "{%0,%1,%2,%3},{%4,%5,%6,%7},{%8,%9},{%0,%1,%2,%3};"
        : "+f"(d[0]), "+f"(d[1]), "+f"(d[2]), "+f"(d[3])
        : "r"(a0), "r"(a1), "r"(a2), "r"(a3), "r"(b0), "r"(b1));
}

// ---------------- dtype probe ----------------
__global__ void k_detect(const unsigned int* __restrict__ p) {
    __shared__ unsigned int s;
    if (threadIdx.x == 0) s = 0u;
    __syncthreads();
    unsigned int v = 0u;
    for (int e = threadIdx.x; e < 2048; e += 256) v |= p[2 * e + 1];
    atomicOr(&s, v);
    __syncthreads();
    if (threadIdx.x == 0) g_is64 = (s == 0u) ? 1 : 0;
}
__device__ __forceinline__ int ld_src(const int* p, int e) {
    return g_is64 ? p[2 * e] : p[e];
}
__device__ __forceinline__ int ld_dst(const int* p, int e) {
    return g_is64 ? p[2 * Ee + 2 * e] : p[Ee + e];
}

// ---------------- weight convert (fp32 -> fp16) ----------------
__global__ void k_cvt_w(const float* __restrict__ W0, const float* __restrict__ Ws,
                        const float* __restrict__ lw) {
    int i = blockIdx.x * 256 + threadIdx.x;
    if (i >= 57344) return;
    float v;
    if (i < 8192) v = W0[i];
    else if (i < 36864) v = Ws[i - 8192];
    else v = lw[i - 36864];
    g_w16[i] = __float2half(v);
}

// ---------------- degree / CSR ----------------
__global__ void k_count(const int* __restrict__ ei) {
    int e = blockIdx.x * 256 + threadIdx.x;
    if (e < Ee) atomicAdd(&g_deg[ld_dst(ei, e)], 1);
}
__global__ void k_scan_block() {
    __shared__ int s[1024];
    int i = blockIdx.x * 1024 + threadIdx.x;
    int v = (i < Nn) ? g_deg[i] : 0;
    if (i < Nn) g_dis[i] = rsqrtf((float)(v + 1));
    s[threadIdx.x] = v;
    __syncthreads();
    for (int off = 1; off < 1024; off <<= 1) {
        int t = (threadIdx.x >= off) ? s[threadIdx.x - off] : 0;
        __syncthreads();
        s[threadIdx.x] += t;
        __syncthreads();
    }
    if (i < Nn) g_rowptr[i] = s[threadIdx.x] - v;
    if (threadIdx.x == 1023) g_bsum[blockIdx.x] = s[1023];
}
__global__ void k_add_off() {
    __shared__ int sb[128];
    int t = threadIdx.x;
    if (t < 128) sb[t] = (t < (int)blockIdx.x) ? g_bsum[t] : 0;
    __syncthreads();
    for (int off = 64; off > 0; off >>= 1) {
        if (t < off) sb[t] += sb[t + off];
        __syncthreads();
    }
    int base = sb[0];
    int i = blockIdx.x * 1024 + t;
    if (i < Nn) {
        int r = g_rowptr[i] + base;
        g_rowptr[i] = r;
        g_cursor[i] = r;
    }
    if (i == 0) g_rowptr[Nn] = Ee;
}
__global__ void k_fill(const int* __restrict__ ei) {
    int e = blockIdx.x * 256 + threadIdx.x;
    if (e >= Ee) return;
    int s = ld_src(ei, e);
    int d = ld_dst(ei, e);
    int p = atomicAdd(&g_cursor[d], 1);
    g_ew[p] = make_int2(s, __float_as_int(g_dis[s] * g_dis[d]));
}

// ------- GEMM0 (fused cvt): tmp[fp16] = fp16(x[N,128]) @ W0_16[128,64] -------
__global__ void k_gemm0_tc(const float* __restrict__ A, const __half* __restrict__ B,
                           __half2* __restrict__ C) {
    __shared__ __align__(16) uint8_t sA[2 * 16384];  // 2 panels: 128 rows x 128B
    __shared__ __align__(16) uint8_t sB[128 * 128];
    const int row0 = blockIdx.x * 128;
    const int tid = threadIdx.x;
    for (int ci = tid; ci < 128 * 32; ci += 256) {
        int r = ci >> 5, c4 = ci & 31;
        float4 v = make_float4(0.f, 0.f, 0.f, 0.f);
        if (row0 + r < Nn) v = ((const float4*)(A + (size_t)(row0 + r) * 128))[c4];
        __half2 h0 = __floats2half2_rn(v.x, v.y);
        __half2 h1 = __floats2half2_rn(v.z, v.w);
        uint2 u = make_uint2(*(uint32_t*)&h0, *(uint32_t*)&h1);
        *(uint2*)(sA + (c4 >> 4) * 16384 + SW(r * 128 + (c4 & 15) * 8)) = u;
    }
    for (int ci = tid; ci < 128 * 8; ci += 256) {
        int r = ci >> 3, c = ci & 7;
        uint4 v = ((const uint4*)(B + r * 64))[c];
        *(uint4*)(sB + SW(r * 128 + c * 16)) = v;
    }
    __syncthreads();

    const int warp = tid >> 5, lane = tid & 31;
    const int m_local = warp * 16;
    const uint32_t sAu = s2u(sA), sBu = s2u(sB);
    const int arow = m_local + (lane & 15);
    const int acol16 = (lane >> 4) * 16;
    float acc[8][4];
#pragma unroll
    for (int i = 0; i < 8; i++)
#pragma unroll
        for (int j = 0; j < 4; j++) acc[i][j] = 0.f;

#pragma unroll
    for (int ks = 0; ks < 8; ks++) {
        int k0 = ks * 16;
        uint32_t a0, a1, a2, a3;
        ldsm_x4(a0, a1, a2, a3,
                sAu + (k0 >> 6) * 16384 + SW(arow * 128 + (k0 & 63) * 2 + acol16));
#pragma unroll
        for (int nt = 0; nt < 8; nt++) {
            uint32_t b0, b1;
            ldsm_x2t(b0, b1, sBu + SW((k0 + (lane & 15)) * 128 + nt * 16));
            mma16816(acc[nt], a0, a1, a2, a3, b0, b1);
        }
    }
    const int g = lane >> 2, t4 = lane & 3;
    int r0 = row0 + m_local + g, r1 = r0 + 8;
    if (r0 < Nn) {
#pragma unroll
        for (int nt = 0; nt < 8; nt++)
            C[(size_t)r0 * 32 + nt * 4 + t4] = __floats2half2_rn(acc[nt][0], acc[nt][1]);
    }
    if (r1 < Nn) {
#pragma unroll
        for (int nt = 0; nt < 8; nt++)
            C[(size_t)r1 * 32 + nt * 4 + t4] = __floats2half2_rn(acc[nt][2], acc[nt][3]);
    }
}

// ---------------- tensor-core GEMM: C[N,64] = A[N,64] @ B[64,64], fp16 ----------------
__global__ void k_gemm_tc(const __half* __restrict__ A, const __half* __restrict__ B,
                          __half2* __restrict__ C) {
    __shared__ __align__(16) uint8_t sA[16384];
    __shared__ __align__(16) uint8_t sB[64 * 128];
    const int row0 = blockIdx.x * 128;
    const int tid = threadIdx.x;
    for (int ci = tid; ci < 128 * 8; ci += 256) {
        int r = ci >> 3, c = ci & 7;
        uint4 v = make_uint4(0, 0, 0, 0);
        if (row0 + r < Nn) v = ((const uint4*)(A + (size_t)(row0 + r) * 64))[c];
        *(uint4*)(sA + SW(r * 128 + c * 16)) = v;
    }
    for (int ci = tid; ci < 64 * 8; ci += 256) {
        int r = ci >> 3, c = ci & 7;
        uint4 v = ((const uint4*)(B + r * 64))[c];
        *(uint4*)(sB + SW(r * 128 + c * 16)) = v;
    }
    __syncthreads();

    const int warp = tid >> 5, lane = tid & 31;
    const int m_local = warp * 16;
    const uint32_t sAu = s2u(sA), sBu = s2u(sB);
    const int arow = m_local + (lane & 15);
    const int acol16 = (lane >> 4) * 16;
    float acc[8][4];
#pragma unroll
    for (int i = 0; i < 8; i++)
#pragma unroll
        for (int j = 0; j < 4; j++) acc[i][j] = 0.f;

#pragma unroll
    for (int ks = 0; ks < 4; ks++) {
        int k0 = ks * 16;
        uint32_t a0, a1, a2, a3;
        ldsm_x4(a0, a1, a2, a3, sAu + SW(arow * 128 + k0 * 2 + acol16));
#pragma unroll
        for (int nt = 0; nt < 8; nt++) {
            uint32_t b0, b1;
            ldsm_x2t(b0, b1, sBu + SW((k0 + (lane & 15)) * 128 + nt * 16));
            mma16816(acc[nt], a0, a1, a2, a3, b0, b1);
        }
    }
    const int g = lane >> 2, t4 = lane & 3;
    int r0 = row0 + m_local + g, r1 = r0 + 8;
    if (r0 < Nn) {
#pragma unroll
        for (int nt = 0; nt < 8; nt++)
            C[(size_t)r0 * 32 + nt * 4 + t4] = __floats2half2_rn(acc[nt][0], acc[nt][1]);
    }
    if (r1 < Nn) {
#pragma unroll
        for (int nt = 0; nt < 8; nt++)
            C[(size_t)r1 * 32 + nt * 4 + t4] = __floats2half2_rn(acc[nt][2], acc[nt][3]);
    }
}

// ------- per-slot JK GEMM: out (+)= h_slot[N,64] @ lw_slot[64,40] (+ lin_b if FIRST) -------
template <bool FIRST>
__global__ void k_jk_slot(const __half* __restrict__ hslot, const __half* __restrict__ lw,
                          const float* __restrict__ lin_b, float* __restrict__ out) {
    __shared__ __align__(16) uint8_t sA[16384];
    __shared__ __align__(16) uint8_t sB[8192];
    const int row0 = blockIdx.x * 128;
    const int tid = threadIdx.x;
    for (int ci = tid; ci < 1024; ci += 256) {
        int r = ci >> 3, c = ci & 7;
        uint4 v = make_uint4(0, 0, 0, 0);
        if (row0 + r < Nn) v = ((const uint4*)(hslot + (size_t)(row0 + r) * 64))[c];
        *(uint4*)(sA + SW(r * 128 + c * 16)) = v;
    }
    for (int ci = tid; ci < 512; ci += 256) {
        int r = ci >> 3, c = ci & 7;
        uint4 v = make_uint4(0, 0, 0, 0);
        if (c < 5) v = ((const uint4*)(lw + (size_t)r * OUTD))[c];
        *(uint4*)(sB + SW(r * 128 + c * 16)) = v;
    }
    __syncthreads();

    const int warp = tid >> 5, lane = tid & 31;
    const int m_local = warp * 16;
    const uint32_t sAu = s2u(sA), sBu = s2u(sB);
    const int arow = m_local + (lane & 15);
    const int acol16 = (lane >> 4) * 16;
    float acc[5][4];
#pragma unroll
    for (int i = 0; i < 5; i++)
#pragma unroll
        for (int j = 0; j < 4; j++) acc[i][j] = 0.f;

#pragma unroll
    for (int ks = 0; ks < 4; ks++) {
        int k0 = ks * 16;
        uint32_t a0, a1, a2, a3;
        ldsm_x4(a0, a1, a2, a3, sAu + SW(arow * 128 + k0 * 2 + acol16));
#pragma unroll
        for (int nt = 0; nt < 5; nt++) {
            uint32_t b0, b1;
            ldsm_x2t(b0, b1, sBu + SW((k0 + (lane & 15)) * 128 + nt * 16));
            mma16816(acc[nt], a0, a1, a2, a3, b0, b1);
        }
    }
    const int g = lane >> 2, t4 = lane & 3;
    int r0 = row0 + m_local + g, r1 = r0 + 8;
#pragma unroll
    for (int nt = 0; nt < 5; nt++) {
        int c = nt * 8 + t4 * 2;
        if (FIRST) {
            float bl0 = lin_b[c], bl1 = lin_b[c + 1];
            if (r0 < Nn)
                *(float2*)&out[(size_t)r0 * OUTD + c] =
                    make_float2(acc[nt][0] + bl0, acc[nt][1] + bl1);
            if (r1 < Nn)
                *(float2*)&out[(size_t)r1 * OUTD + c] =
                    make_float2(acc[nt][2] + bl0, acc[nt][3] + bl1);
        } else {
            if (r0 < Nn) {
                float2 p = *(float2*)&out[(size_t)r0 * OUTD + c];
                *(float2*)&out[(size_t)r0 * OUTD + c] =
                    make_float2(p.x + acc[nt][0], p.y + acc[nt][1]);
            }
            if (r1 < Nn) {
                float2 p = *(float2*)&out[(size_t)r1 * OUTD + c];
                *(float2*)&out[(size_t)r1 * OUTD + c] =
                    make_float2(p.x + acc[nt][2], p.y + acc[nt][3]);
            }
        }
    }
}

// ------ aggregation: 4 nodes/warp, 8 lanes/node, 16B (8 halves) per lane ------
__global__ void k_aggregate(const float* __restrict__ bias, uint4* __restrict__ hdst) {
    int warp = (blockIdx.x * 256 + threadIdx.x) >> 5;
    int lane = threadIdx.x & 31;
    int node = warp * 4 + (lane >> 3);
    if (node >= Nn) return;
    int fl = lane & 7;  // 16B chunk within 128B row
    const uint4* tp = (const uint4*)g_tmp;
    float a0 = 0.f, a1 = 0.f, a2 = 0.f, a3 = 0.f, a4 = 0.f, a5 = 0.f, a6 = 0.f, a7 = 0.f;
    int beg = g_rowptr[node], end = g_rowptr[node + 1];
    for (int j = beg; j < end; j++) {
        int2 e = __ldg(&g_ew[j]);
        float wt = __int_as_float(e.y);
        uint4 v = __ldg(&tp[(size_t)e.x * 8 + fl]);
        float2 p0 = __half22float2(*(__half2*)&v.x);
        float2 p1 = __half22float2(*(__half2*)&v.y);
        float2 p2 = __half22float2(*(__half2*)&v.z);
        float2 p3 = __half22float2(*(__half2*)&v.w);
        a0 += wt * p0.x; a1 += wt * p0.y;
        a2 += wt * p1.x; a3 += wt * p1.y;
        a4 += wt * p2.x; a5 += wt * p2.y;
        a6 += wt * p3.x; a7 += wt * p3.y;
    }
    float d = g_dis[node];
    float sw = d * d;  // self-loop norm
    {
        uint4 v = tp[(size_t)node * 8 + fl];
        float2 p0 = __half22float2(*(__half2*)&v.x);
        float2 p1 = __half22float2(*(__half2*)&v.y);
        float2 p2 = __half22float2(*(__half2*)&v.z);
        float2 p3 = __half22float2(*(__half2*)&v.w);
        a0 += sw * p0.x; a1 += sw * p0.y;
        a2 += sw * p1.x; a3 += sw * p1.y;
        a4 += sw * p2.x; a5 += sw * p2.y;
        a6 += sw * p3.x; a7 += sw * p3.y;
    }
    const float4 b0 = *(const float4*)&bias[fl * 8];
    const float4 b1 = *(const float4*)&bias[fl * 8 + 4];
    __half2 h0 = __floats2half2_rn(fmaxf(a0 + b0.x, 0.f), fmaxf(a1 + b0.y, 0.f));
    __half2 h1 = __floats2half2_rn(fmaxf(a2 + b0.z, 0.f), fmaxf(a3 + b0.w, 0.f));
    __half2 h2 = __floats2half2_rn(fmaxf(a4 + b1.x, 0.f), fmaxf(a5 + b1.y, 0.f));
    __half2 h3 = __floats2half2_rn(fmaxf(a6 + b1.z, 0.f), fmaxf(a7 + b1.w, 0.f));
    hdst[(size_t)node * 8 + fl] =
        make_uint4(*(uint32_t*)&h0, *(uint32_t*)&h1, *(uint32_t*)&h2, *(uint32_t*)&h3);
}

extern "C" void kernel_launch(void* const* d_in, const int* in_sizes, int n_in,
                              void* d_out, int out_size) {
    const float* x = nullptr;
    const float* W0 = nullptr;
    const float* Ws = nullptr;
    const float* bs = nullptr;
    const float* lin_w = nullptr;
    const float* lin_b = nullptr;
    const int*   ei = nullptr;
    for (int i = 0; i < n_in; i++) {
        switch (in_sizes[i]) {
            case 12800000: x     = (const float*)d_in[i]; break;
            case 8192:     W0    = (const float*)d_in[i]; break;
            case 28672:    Ws    = (const float*)d_in[i]; break;
            case 512:      bs    = (const float*)d_in[i]; break;
            case 20480:    lin_w = (const float*)d_in[i]; break;
            case 40:       lin_b = (const float*)d_in[i]; break;
            case 3200000:
            case 6400000:  ei    = (const int*)d_in[i];   break;
            default: break;
        }
    }
    if (!(x && W0 && Ws && bs && lin_w && lin_b && ei)) {
        x     = (const float*)d_in[0];
        W0    = (const float*)d_in[1];
        Ws    = (const float*)d_in[2];
        bs    = (const float*)d_in[3];
        lin_w = (const float*)d_in[4];
        lin_b = (const float*)d_in[5];
        ei    = (const int*)d_in[6];
    }
    float* out = (float*)d_out;

    // device-symbol addresses for host-side kernel args (R7 root cause)
    __half *w16_d, *tmp_d, *hall_d;
    int* deg_d;
    cudaGetSymbolAddress((void**)&w16_d, g_w16);
    cudaGetSymbolAddress((void**)&tmp_d, g_tmp);
    cudaGetSymbolAddress((void**)&hall_d, g_hall);
    cudaGetSymbolAddress((void**)&deg_d, g_deg);

    // streams/events: created once (host resources; identical work every call)
    static cudaStream_t s1 = nullptr, s2 = nullptr;
    static cudaEvent_t e_root, e_csr, e_agg[Ll], e_jk;
    if (!s1) {
        cudaStreamCreateWithFlags(&s1, cudaStreamNonBlocking);
        cudaStreamCreateWithFlags(&s2, cudaStreamNonBlocking);
        cudaEventCreateWithFlags(&e_root, cudaEventDisableTiming);
        cudaEventCreateWithFlags(&e_csr, cudaEventDisableTiming);
        for (int l = 0; l < Ll; l++)
            cudaEventCreateWithFlags(&e_agg[l], cudaEventDisableTiming);
        cudaEventCreateWithFlags(&e_jk, cudaEventDisableTiming);
    }

    cudaStreamCaptureStatus cst = cudaStreamCaptureStatusNone;
    cudaError_t qe = cudaStreamIsCapturing((cudaStream_t)0, &cst);
    bool capturing = (qe != cudaSuccess) || (cst != cudaStreamCaptureStatusNone);
    if (qe != cudaSuccess) (void)cudaGetLastError();

    const int NB = (Nn + 1023) / 1024;       // 98
    const int GEMM_GRID = (Nn + 127) / 128;  // 782
    const int AGG_GRID = (Nn + 31) / 32;

    // fork s1 (CSR build) off the capture stream
    cudaEventRecord(e_root, 0);
    cudaStreamWaitEvent(s1, e_root, 0);

    // s1: CSR chain
    k_detect<<<1, 256, 0, s1>>>((const unsigned int*)ei);
    cudaMemsetAsync(deg_d, 0, Nn * sizeof(int), s1);
    k_count<<<(Ee + 255) / 256, 256, 0, s1>>>(ei);
    k_scan_block<<<NB, 1024, 0, s1>>>();
    k_add_off<<<NB, 1024, 0, s1>>>();
    k_fill<<<(Ee + 255) / 256, 256, 0, s1>>>(ei);
    cudaEventRecord(e_csr, s1);

    // stream 0 (main): weights + gemm0 concurrently with CSR build
    k_cvt_w<<<224, 256>>>(W0, Ws, lin_w);
    k_gemm0_tc<<<GEMM_GRID, 256>>>(x, w16_d, (__half2*)tmp_d);
    cudaStreamWaitEvent(0, e_csr, 0);  // join CSR before aggregation

    for (int l = 0; l < Ll; l++) {
        __half* slot = hall_d + (size_t)l * Nn * Hd;
        k_aggregate<<<AGG_GRID, 256>>>(bs + l * Hd, (uint4*)slot);
        cudaEventRecord(e_agg[l], 0);
        // JK slot GEMM on s2, overlapped with the main chain
        cudaStreamWaitEvent(s2, e_agg[l], 0);
        if (l == 0)
            k_jk_slot<true><<<GEMM_GRID, 256, 0, s2>>>(slot, w16_d + 36864, lin_b, out);
        else
            k_jk_slot<false><<<GEMM_GRID, 256, 0, s2>>>(
                slot, w16_d + 36864 + (size_t)l * Hd * OUTD, lin_b, out);
        if (l < Ll - 1)
            k_gemm_tc<<<GEMM_GRID, 256>>>(slot, w16_d + 8192 + (size_t)l * 4096,
                                          (__half2*)tmp_d);
    }
    cudaEventRecord(e_jk, s2);
    cudaStreamWaitEvent(0, e_jk, 0);  // join JK stream

    // -------- zero-output tripwire (correctness call only; never during capture) --------
    if (!capturing) {
        static float ho[8];
        cudaMemcpyAsync(ho, out, 8 * sizeof(float), cudaMemcpyDeviceToHost, 0);
        cudaError_t qs = cudaErrorNotReady;
        for (long it = 0; it < 4000000000L; it++) {
            qs = cudaStreamQuery((cudaStream_t)0);
            if (qs != cudaErrorNotReady) break;
        }
        float mx = 0.f;
        for (int i = 0; i < 8; i++) mx = fmaxf(mx, fabsf(ho[i]));
        if (qs != cudaSuccess || mx < 1e-6f) {
            fprintf(stderr, "[diag] TRIPWIRE mx=%g q=%s out=%g %g %g %g\n", mx,
                    cudaGetErrorName(qs), ho[0], ho[1], ho[2], ho[3]);
            fflush(stderr);
            abort();
        }
    }
}